// round 9
// baseline (speedup 1.0000x reference)
#include <cuda_runtime.h>
#include <cuda_bf16.h>

// ---------------------------------------------------------------------------
// AIMNet2 interaction module — per-atom formulation + tensor-core linear.
//
//   radial[i]   = Σ_{p∈i} f_p * A[j_p]                  (segment sum, fp32)
//   S[i,c,:]    = Σ_{p∈i} u[p,c] * f_p * A[j_p]         (segment sum, fp32)
//   T           = S @ W^T                               (3xTF32 mma.sync GEMM)
//   out[i]      = [ sqrt(Σ_c (T[i,c,:]+deg_i*b)^2 + 1e-12), radial[i] ]
//
// Pipeline: hist -> shuffle scan -> scatter (sort pairs by idx_i)
//           -> gather (1 warp/atom, register segment sums, writes S + radial)
//           -> persistent GEMM+finalize (W hi/lo in smem, T stays in smem).
// ---------------------------------------------------------------------------

#define FDIM 128
#define MAX_ATOMS 20480
#define MAX_PAIRS 393216

typedef unsigned int u32;

__device__ int g_count[MAX_ATOMS + 1];
__device__ int g_start[MAX_ATOMS + 1];
__device__ int g_cursor[MAX_ATOMS + 1];
__device__ int g_sorted[MAX_PAIRS];
__device__ __align__(16) float g_S[(size_t)MAX_ATOMS * 3 * FDIM];   // [3N,128]

// ---------------------------------------------------------------------------
__global__ void zero_counts_kernel(int n_atoms) {
    int i = blockIdx.x * blockDim.x + threadIdx.x;
    if (i <= n_atoms) g_count[i] = 0;
}

__global__ void hist_kernel(const int* __restrict__ pl, int n_pairs) {
    int p = blockIdx.x * blockDim.x + threadIdx.x;
    if (p < n_pairs) atomicAdd(&g_count[pl[p]], 1);
}

// Single-block warp-shuffle scan: counts -> exclusive g_start (+ cursor copy).
__global__ void scan_kernel(int n_atoms) {
    __shared__ int wsum[32];
    __shared__ int s_total;
    const int tid = threadIdx.x;
    const int lane = tid & 31;
    const int w = tid >> 5;
    int carry = 0;
    for (int base = 0; base < n_atoms; base += 1024) {
        int idx = base + tid;
        int v = (idx < n_atoms) ? g_count[idx] : 0;
        int incl = v;
        #pragma unroll
        for (int off = 1; off < 32; off <<= 1) {
            int t = __shfl_up_sync(0xffffffffu, incl, off);
            if (lane >= off) incl += t;
        }
        if (lane == 31) wsum[w] = incl;
        __syncthreads();
        if (w == 0) {
            int s = wsum[lane];
            int i2 = s;
            #pragma unroll
            for (int off = 1; off < 32; off <<= 1) {
                int t = __shfl_up_sync(0xffffffffu, i2, off);
                if (lane >= off) i2 += t;
            }
            wsum[lane] = i2 - s;           // exclusive warp offset
            if (lane == 31) s_total = i2;  // tile total
        }
        __syncthreads();
        int excl = carry + wsum[w] + incl - v;
        if (idx < n_atoms) { g_start[idx] = excl; g_cursor[idx] = excl; }
        carry += s_total;
        __syncthreads();
    }
    if (tid == 0) g_start[n_atoms] = carry;
}

__global__ void scatter_kernel(const int* __restrict__ pl, int n_pairs) {
    int p = blockIdx.x * blockDim.x + threadIdx.x;
    if (p < n_pairs) {
        int pos = atomicAdd(&g_cursor[pl[p]], 1);
        g_sorted[pos] = p;
    }
}

// ---------------------------------------------------------------------------
// Gather: one warp per atom; register segment sums -> S rows + radial out.
// Lane owns features f = 4*lane .. 4*lane+3.
// ---------------------------------------------------------------------------
__global__ void __launch_bounds__(256)
gather_kernel(const float* __restrict__ A,
              const int*   __restrict__ pl,
              const float* __restrict__ fc,
              const float* __restrict__ rij,
              float*       __restrict__ out,
              int n_pairs, int n_atoms)
{
    const int wid  = threadIdx.x >> 5;
    const int lane = threadIdx.x & 31;
    const int atom = blockIdx.x * 8 + wid;
    if (atom >= n_atoms) return;

    const int* pl_j = pl + n_pairs;
    const int fbase = 4 * lane;
    const int s0 = g_start[atom];
    const int s1 = g_start[atom + 1];

    float4 racc = make_float4(0.f, 0.f, 0.f, 0.f);
    float4 sx = racc, sy = racc, sz = racc;

    for (int base = s0; base < s1; base += 32) {
        int m = s1 - base; if (m > 32) m = 32;
        int jj = 0; float fq = 0.f, ux = 0.f, uy = 0.f, uz = 0.f;
        if (lane < m) {
            int pid = g_sorted[base + lane];
            jj = pl_j[pid];
            fq = __ldg(fc + pid);
            float rx = __ldg(rij + 3 * pid + 0);
            float ry = __ldg(rij + 3 * pid + 1);
            float rz = __ldg(rij + 3 * pid + 2);
            float inv = rsqrtf(rx * rx + ry * ry + rz * rz);
            ux = rx * inv; uy = ry * inv; uz = rz * inv;
        }
        // software-pipelined gather (MLP=2)
        float4 a_cur = make_float4(0.f, 0.f, 0.f, 0.f);
        {
            int j0 = __shfl_sync(0xffffffffu, jj, 0);
            if (m > 0)
                a_cur = *reinterpret_cast<const float4*>(A + (size_t)j0 * FDIM + fbase);
        }
        for (int q = 0; q < m; q++) {
            float4 a = a_cur;
            if (q + 1 < m) {
                int jn = __shfl_sync(0xffffffffu, jj, q + 1);
                a_cur = *reinterpret_cast<const float4*>(A + (size_t)jn * FDIM + fbase);
            }
            float f_ = __shfl_sync(0xffffffffu, fq, q);
            float x  = __shfl_sync(0xffffffffu, ux, q);
            float y  = __shfl_sync(0xffffffffu, uy, q);
            float z  = __shfl_sync(0xffffffffu, uz, q);
            float wx = f_ * a.x, wy = f_ * a.y, wz = f_ * a.z, ww = f_ * a.w;
            racc.x += wx; racc.y += wy; racc.z += wz; racc.w += ww;
            sx.x = fmaf(x, wx, sx.x); sx.y = fmaf(x, wy, sx.y);
            sx.z = fmaf(x, wz, sx.z); sx.w = fmaf(x, ww, sx.w);
            sy.x = fmaf(y, wx, sy.x); sy.y = fmaf(y, wy, sy.y);
            sy.z = fmaf(y, wz, sy.z); sy.w = fmaf(y, ww, sy.w);
            sz.x = fmaf(z, wx, sz.x); sz.y = fmaf(z, wy, sz.y);
            sz.z = fmaf(z, wz, sz.z); sz.w = fmaf(z, ww, sz.w);
        }
    }

    // radial half of the output
    *reinterpret_cast<float4*>(out + (size_t)atom * (2 * FDIM) + FDIM + fbase) = racc;
    // S rows (atom*3 + c)
    float* srow = g_S + (size_t)atom * 3 * FDIM + fbase;
    *reinterpret_cast<float4*>(srow)            = sx;
    *reinterpret_cast<float4*>(srow + FDIM)     = sy;
    *reinterpret_cast<float4*>(srow + 2 * FDIM) = sz;
}

// ---------------------------------------------------------------------------
// GEMM + finalize: T = S @ W^T via 3xTF32 mma.sync.m16n8k8, epilogue computes
// vector norms in smem. Persistent blocks; W hi/lo staged once per block.
//
// Block = 192 threads (6 warps). Group = 16 atoms = 48 S-rows.
// warp w: m-subtile = (w%3)*16 rows, n-half = (w/3)*64 cols.
// ---------------------------------------------------------------------------
#define GB_THREADS 192
#define GB_ATOMS 16
#define GROUP_ROWS 48
#define WSM_S 132
#define GEMM_SMEM ((2 * FDIM * WSM_S + GROUP_ROWS * WSM_S) * 4)

__device__ __forceinline__ u32 f2tf32(float v) {
    u32 r; asm("cvt.rna.tf32.f32 %0, %1;" : "=r"(r) : "f"(v)); return r;
}
__device__ __forceinline__ void mma_tf32(float acc[4],
                                         u32 a0, u32 a1, u32 a2, u32 a3,
                                         u32 b0, u32 b1) {
    asm volatile("mma.sync.aligned.m16n8k8.row.col.f32.tf32.tf32.f32 "
                 "{%0,%1,%2,%3}, {%4,%5,%6,%7}, {%8,%9}, {%0,%1,%2,%3};"
                 : "+f"(acc[0]), "+f"(acc[1]), "+f"(acc[2]), "+f"(acc[3])
                 : "r"(a0), "r"(a1), "r"(a2), "r"(a3), "r"(b0), "r"(b1));
}

__global__ void __launch_bounds__(GB_THREADS, 1)
gemm_finalize_kernel(const float* __restrict__ W,
                     const float* __restrict__ bvec,
                     float*       __restrict__ out,
                     int n_atoms)
{
    extern __shared__ float sm[];
    float* Whi = sm;                        // [128][132]  W[g][f] tf32-rounded
    float* Wlo = sm + FDIM * WSM_S;         // [128][132]  residual
    float* ST  = sm + 2 * FDIM * WSM_S;     // [48][132]   S tile, then T tile

    const int tid  = threadIdx.x;
    const int lane = tid & 31;
    const int wid  = tid >> 5;

    // Stage W hi/lo once.
    for (int idx = tid; idx < FDIM * FDIM; idx += GB_THREADS) {
        int g = idx >> 7, f = idx & (FDIM - 1);
        float w = W[idx];
        float hf = __uint_as_float(f2tf32(w));
        Whi[g * WSM_S + f] = hf;
        Wlo[g * WSM_S + f] = w - hf;
    }
    __syncthreads();

    const int mbase = (wid % 3) * 16;
    const int n0    = (wid / 3) * 64;
    const int r0    = mbase + (lane >> 2);
    const int c0    = lane & 3;
    const int nrows_tot = 3 * n_atoms;
    const int ngroups = (n_atoms + GB_ATOMS - 1) / GB_ATOMS;

    for (int grp = blockIdx.x; grp < ngroups; grp += gridDim.x) {
        const int m0 = grp * GROUP_ROWS;

        // ---- stage S tile [48][128] (coalesced float4) ----
        for (int idx = tid; idx < GROUP_ROWS * 32; idx += GB_THREADS) {
            int r = idx >> 5, l4 = (idx & 31) * 4;
            float4 v = make_float4(0.f, 0.f, 0.f, 0.f);
            if (m0 + r < nrows_tot)
                v = *reinterpret_cast<const float4*>(g_S + (size_t)(m0 + r) * FDIM + l4);
            *reinterpret_cast<float4*>(ST + r * WSM_S + l4) = v;
        }
        __syncthreads();

        // ---- 3xTF32 GEMM: 16m x 64n per warp, K=128 ----
        float acc[8][4];
        #pragma unroll
        for (int nt = 0; nt < 8; nt++)
            acc[nt][0] = acc[nt][1] = acc[nt][2] = acc[nt][3] = 0.f;

        #pragma unroll 2
        for (int kc = 0; kc < 16; kc++) {
            int k0 = kc * 8;
            float fa0 = ST[r0 * WSM_S + k0 + c0];
            float fa1 = ST[(r0 + 8) * WSM_S + k0 + c0];
            float fa2 = ST[r0 * WSM_S + k0 + c0 + 4];
            float fa3 = ST[(r0 + 8) * WSM_S + k0 + c0 + 4];
            u32 ah0 = f2tf32(fa0), ah1 = f2tf32(fa1);
            u32 ah2 = f2tf32(fa2), ah3 = f2tf32(fa3);
            u32 al0 = __float_as_uint(fa0 - __uint_as_float(ah0));
            u32 al1 = __float_as_uint(fa1 - __uint_as_float(ah1));
            u32 al2 = __float_as_uint(fa2 - __uint_as_float(ah2));
            u32 al3 = __float_as_uint(fa3 - __uint_as_float(ah3));

            #pragma unroll
            for (int nt = 0; nt < 8; nt++) {
                int g  = n0 + nt * 8 + (lane >> 2);
                int kk = k0 + c0;
                u32 bh0 = __float_as_uint(Whi[g * WSM_S + kk]);
                u32 bh1 = __float_as_uint(Whi[g * WSM_S + kk + 4]);
                u32 bl0 = __float_as_uint(Wlo[g * WSM_S + kk]);
                u32 bl1 = __float_as_uint(Wlo[g * WSM_S + kk + 4]);
                mma_tf32(acc[nt], ah0, ah1, ah2, ah3, bh0, bh1);
                mma_tf32(acc[nt], ah0, ah1, ah2, ah3, bl0, bl1);
                mma_tf32(acc[nt], al0, al1, al2, al3, bh0, bh1);
            }
        }
        __syncthreads();   // all ST reads done before overwrite with T

        // ---- dump T into ST ----
        #pragma unroll
        for (int nt = 0; nt < 8; nt++) {
            int col = n0 + nt * 8 + 2 * c0;
            int row = mbase + (lane >> 2);
            ST[row * WSM_S + col]           = acc[nt][0];
            ST[row * WSM_S + col + 1]       = acc[nt][1];
            ST[(row + 8) * WSM_S + col]     = acc[nt][2];
            ST[(row + 8) * WSM_S + col + 1] = acc[nt][3];
        }
        __syncthreads();

        // ---- epilogue: bias + norm over 3 components ----
        const int a0 = grp * GB_ATOMS;
        for (int t = tid; t < GB_ATOMS * 32; t += GB_THREADS) {
            int al_ = t >> 5, l4 = (t & 31) * 4;
            int a = a0 + al_;
            if (a < n_atoms) {
                float4 vx = *reinterpret_cast<float4*>(ST + (al_ * 3 + 0) * WSM_S + l4);
                float4 vy = *reinterpret_cast<float4*>(ST + (al_ * 3 + 1) * WSM_S + l4);
                float4 vz = *reinterpret_cast<float4*>(ST + (al_ * 3 + 2) * WSM_S + l4);
                float deg = (float)(g_start[a + 1] - g_start[a]);
                float4 bb = __ldg(reinterpret_cast<const float4*>(bvec + l4));
                float4 r;
                {
                    float db = deg * bb.x, x = vx.x + db, y = vy.x + db, z = vz.x + db;
                    r.x = sqrtf(x * x + y * y + z * z + 1e-12f);
                }
                {
                    float db = deg * bb.y, x = vx.y + db, y = vy.y + db, z = vz.y + db;
                    r.y = sqrtf(x * x + y * y + z * z + 1e-12f);
                }
                {
                    float db = deg * bb.z, x = vx.z + db, y = vy.z + db, z = vz.z + db;
                    r.z = sqrtf(x * x + y * y + z * z + 1e-12f);
                }
                {
                    float db = deg * bb.w, x = vx.w + db, y = vy.w + db, z = vz.w + db;
                    r.w = sqrtf(x * x + y * y + z * z + 1e-12f);
                }
                *reinterpret_cast<float4*>(out + (size_t)a * (2 * FDIM) + l4) = r;
            }
        }
        __syncthreads();   // before next group's S staging overwrites ST
    }
}

// ---------------------------------------------------------------------------
extern "C" void kernel_launch(void* const* d_in, const int* in_sizes, int n_in,
                              void* d_out, int out_size) {
    const float* A   = (const float*)d_in[0];
    const int*   pl  = (const int*)d_in[1];
    const float* fc  = (const float*)d_in[2];
    const float* rij = (const float*)d_in[3];
    const float* W   = (const float*)d_in[4];
    const float* b   = (const float*)d_in[5];
    float* out = (float*)d_out;

    int n_atoms = in_sizes[0] / FDIM;
    int n_pairs = in_sizes[2];

    static int smem_set = 0;
    if (!smem_set) {
        cudaFuncSetAttribute(gemm_finalize_kernel,
                             cudaFuncAttributeMaxDynamicSharedMemorySize, GEMM_SMEM);
        smem_set = 1;
    }

    int pb = (n_pairs + 255) / 256;
    zero_counts_kernel<<<(n_atoms + 256) / 256, 256>>>(n_atoms);
    hist_kernel<<<pb, 256>>>(pl, n_pairs);
    scan_kernel<<<1, 1024>>>(n_atoms);
    scatter_kernel<<<pb, 256>>>(pl, n_pairs);
    gather_kernel<<<(n_atoms + 7) / 8, 256>>>(A, pl, fc, rij, out,
                                              n_pairs, n_atoms);
    gemm_finalize_kernel<<<148, GB_THREADS, GEMM_SMEM>>>(W, b, out, n_atoms);
}

// round 12
// speedup vs baseline: 1.2937x; 1.2937x over previous
#include <cuda_runtime.h>
#include <cuda_bf16.h>

// ---------------------------------------------------------------------------
// AIMNet2 interaction module — fused per-atom formulation (FFMA2 matvec).
//
//   radial[i]   = Σ_{p∈i} f_p * A[j_p]                  (segment sum)
//   s[i,c,:]    = Σ_{p∈i} u[p,c] * f_p * A[j_p]         (segment sum)
//   vec[i,c,:]  = W @ s[i,c,:] + deg(i)*b               (3 matvecs/atom)
//   out[i]      = [ sqrt(Σ_c vec² + 1e-12), radial ]
//
// Pipeline: hist -> shuffle scan -> scatter (pairs sorted by idx_i) ->
//   fused kernel: per warp, chunks of 4 atoms: register segment-sum gather,
//   then a 4-atom-batched matvec using packed fma.rn.f32x2 with W staged in
//   smem as pre-packed g-pairs (no per-use packing).
// ---------------------------------------------------------------------------

#define FDIM 128
#define MAX_ATOMS 20480
#define MAX_PAIRS 393216
#define CHUNK 4
#define MAIN_BLOCKS 148
#define WARPS_PER_BLOCK 16
#define MAIN_THREADS (WARPS_PER_BLOCK * 32)

typedef unsigned int u32;
typedef unsigned long long ull;

__device__ int g_count[MAX_ATOMS + 1];
__device__ int g_start[MAX_ATOMS + 1];
__device__ int g_cursor[MAX_ATOMS + 1];
__device__ int g_sorted[MAX_PAIRS];

__device__ __forceinline__ ull dup2(float v) {
    ull d; asm("mov.b64 %0, {%1, %1};" : "=l"(d) : "f"(v)); return d;
}
__device__ __forceinline__ ull pack2(float lo, float hi) {
    ull d; asm("mov.b64 %0, {%1, %2};" : "=l"(d) : "f"(lo), "f"(hi)); return d;
}
__device__ __forceinline__ void unpack2(ull v, float& lo, float& hi) {
    asm("mov.b64 {%0, %1}, %2;" : "=f"(lo), "=f"(hi) : "l"(v));
}
#define FMA2(acc, a, b) \
    asm("fma.rn.f32x2 %0, %1, %2, %0;" : "+l"(acc) : "l"(a), "l"(b))

// ---------------------------------------------------------------------------
__global__ void zero_counts_kernel(int n_atoms) {
    int i = blockIdx.x * blockDim.x + threadIdx.x;
    if (i <= n_atoms) g_count[i] = 0;
}

__global__ void hist_kernel(const int* __restrict__ pl, int n_pairs) {
    int p = blockIdx.x * blockDim.x + threadIdx.x;
    if (p < n_pairs) atomicAdd(&g_count[pl[p]], 1);
}

// Single-block warp-shuffle scan: counts -> exclusive g_start (+ cursor copy).
__global__ void scan_kernel(int n_atoms) {
    __shared__ int wsum[32];
    __shared__ int s_total;
    const int tid = threadIdx.x;
    const int lane = tid & 31;
    const int w = tid >> 5;
    int carry = 0;
    for (int base = 0; base < n_atoms; base += 1024) {
        int idx = base + tid;
        int v = (idx < n_atoms) ? g_count[idx] : 0;
        int incl = v;
        #pragma unroll
        for (int off = 1; off < 32; off <<= 1) {
            int t = __shfl_up_sync(0xffffffffu, incl, off);
            if (lane >= off) incl += t;
        }
        if (lane == 31) wsum[w] = incl;
        __syncthreads();
        if (w == 0) {
            int s = wsum[lane];
            int i2 = s;
            #pragma unroll
            for (int off = 1; off < 32; off <<= 1) {
                int t = __shfl_up_sync(0xffffffffu, i2, off);
                if (lane >= off) i2 += t;
            }
            wsum[lane] = i2 - s;
            if (lane == 31) s_total = i2;
        }
        __syncthreads();
        int excl = carry + wsum[w] + incl - v;
        if (idx < n_atoms) { g_start[idx] = excl; g_cursor[idx] = excl; }
        carry += s_total;
        __syncthreads();
    }
    if (tid == 0) g_start[n_atoms] = carry;
}

__global__ void scatter_kernel(const int* __restrict__ pl, int n_pairs) {
    int p = blockIdx.x * blockDim.x + threadIdx.x;
    if (p < n_pairs) {
        int pos = atomicAdd(&g_cursor[pl[p]], 1);
        g_sorted[pos] = p;
    }
}

// ---------------------------------------------------------------------------
// Main fused kernel.
// smem: WT2 [128 f][64 gpair] ull  = pre-packed {W[2gp,f], W[2gp+1,f]}
//       SS  [16 warps][CHUNK][3][128] float  = staged s vectors
// ---------------------------------------------------------------------------
#define SS_PER_ATOM (3 * FDIM)                 // floats
#define SS_PER_WARP (CHUNK * SS_PER_ATOM)
#define SMEM_MAIN (FDIM * 64 * 8 + WARPS_PER_BLOCK * SS_PER_WARP * 4)  // 163,840

__global__ void __launch_bounds__(MAIN_THREADS, 1)
main_kernel(const float* __restrict__ A,
            const int*   __restrict__ pl,
            const float* __restrict__ fc,
            const float* __restrict__ rij,
            const float* __restrict__ W,
            const float* __restrict__ bvec,
            float*       __restrict__ out,
            int n_pairs, int n_atoms)
{
    extern __shared__ char smem_raw[];
    ull*   WT2 = reinterpret_cast<ull*>(smem_raw);            // [128][64]
    float* SS  = reinterpret_cast<float*>(smem_raw + FDIM * 64 * 8);

    const int tid  = threadIdx.x;
    const int wid  = tid >> 5;
    const int lane = tid & 31;

    // Stage W as packed g-pairs: WT2[f][gp] = {W[2gp][f], W[2gp+1][f]}
    for (int idx = tid; idx < FDIM * 64; idx += MAIN_THREADS) {
        int f = idx >> 6, gp = idx & 63;
        WT2[f * 64 + gp] = pack2(__ldg(W + (2 * gp) * FDIM + f),
                                 __ldg(W + (2 * gp + 1) * FDIM + f));
    }
    __syncthreads();

    float* sw = SS + wid * SS_PER_WARP;
    const int* pl_j = pl + n_pairs;
    const int fbase = 4 * lane;
    const int n_chunks = (n_atoms + CHUNK - 1) / CHUNK;
    const int wstep = gridDim.x * WARPS_PER_BLOCK;

    for (int ch = blockIdx.x * WARPS_PER_BLOCK + wid; ch < n_chunks; ch += wstep) {
        const int abase = ch * CHUNK;
        float degs[CHUNK];

        __syncwarp();   // previous chunk's matvec reads of sw are done

        // ================= gather: 4 atoms, register segment sums ==========
        #pragma unroll
        for (int a = 0; a < CHUNK; a++) {
            const int atom = abase + a;
            float4 racc = make_float4(0.f, 0.f, 0.f, 0.f);
            float4 sx = racc, sy = racc, sz = racc;
            degs[a] = 0.f;

            if (atom < n_atoms) {
                const int s0 = g_start[atom];
                const int s1 = g_start[atom + 1];
                degs[a] = (float)(s1 - s0);

                for (int base = s0; base < s1; base += 32) {
                    int m = s1 - base; if (m > 32) m = 32;
                    int jj = 0; float fq = 0.f, ux = 0.f, uy = 0.f, uz = 0.f;
                    if (lane < m) {
                        int pid = g_sorted[base + lane];
                        jj = pl_j[pid];
                        fq = __ldg(fc + pid);
                        float rx = __ldg(rij + 3 * pid + 0);
                        float ry = __ldg(rij + 3 * pid + 1);
                        float rz = __ldg(rij + 3 * pid + 2);
                        float inv = rsqrtf(rx * rx + ry * ry + rz * rz);
                        ux = rx * inv; uy = ry * inv; uz = rz * inv;
                    }
                    // double-buffered gather of A rows
                    float4 a_cur = make_float4(0.f, 0.f, 0.f, 0.f);
                    {
                        int j0 = __shfl_sync(0xffffffffu, jj, 0);
                        if (m > 0)
                            a_cur = *reinterpret_cast<const float4*>(
                                A + (size_t)j0 * FDIM + fbase);
                    }
                    for (int q = 0; q < m; q++) {
                        float4 av = a_cur;
                        if (q + 1 < m) {
                            int jn = __shfl_sync(0xffffffffu, jj, q + 1);
                            a_cur = *reinterpret_cast<const float4*>(
                                A + (size_t)jn * FDIM + fbase);
                        }
                        float f_ = __shfl_sync(0xffffffffu, fq, q);
                        float x  = __shfl_sync(0xffffffffu, ux, q);
                        float y  = __shfl_sync(0xffffffffu, uy, q);
                        float z  = __shfl_sync(0xffffffffu, uz, q);
                        float wx = f_ * av.x, wy = f_ * av.y;
                        float wz = f_ * av.z, ww = f_ * av.w;
                        racc.x += wx; racc.y += wy; racc.z += wz; racc.w += ww;
                        sx.x = fmaf(x, wx, sx.x); sx.y = fmaf(x, wy, sx.y);
                        sx.z = fmaf(x, wz, sx.z); sx.w = fmaf(x, ww, sx.w);
                        sy.x = fmaf(y, wx, sy.x); sy.y = fmaf(y, wy, sy.y);
                        sy.z = fmaf(y, wz, sy.z); sy.w = fmaf(y, ww, sy.w);
                        sz.x = fmaf(z, wx, sz.x); sz.y = fmaf(z, wy, sz.y);
                        sz.z = fmaf(z, wz, sz.z); sz.w = fmaf(z, ww, sz.w);
                    }
                }
                // radial half of the output
                *reinterpret_cast<float4*>(
                    out + (size_t)atom * (2 * FDIM) + FDIM + fbase) = racc;
            }
            // stage s (zeros for OOB atoms keep matvec unguarded)
            float* swa = sw + a * SS_PER_ATOM;
            *reinterpret_cast<float4*>(swa + 0 * FDIM + fbase) = sx;
            *reinterpret_cast<float4*>(swa + 1 * FDIM + fbase) = sy;
            *reinterpret_cast<float4*>(swa + 2 * FDIM + fbase) = sz;
        }
        __syncwarp();

        // ================= matvec: 4 atoms batched, packed f32x2 ===========
        // acc[a*6 + {0,1}]=x-comp g-lo/hi, {2,3}=y, {4,5}=z ; lane owns g=4l..4l+3
        ull acc[CHUNK * 6];
        #pragma unroll
        for (int k = 0; k < CHUNK * 6; k++) acc[k] = 0;

        const ull* wrow = WT2 + 2 * lane;

        #pragma unroll 2
        for (int f4 = 0; f4 < FDIM / 4; f4++) {
            ulonglong2 w0 = *reinterpret_cast<const ulonglong2*>(wrow + (4 * f4 + 0) * 64);
            ulonglong2 w1 = *reinterpret_cast<const ulonglong2*>(wrow + (4 * f4 + 1) * 64);
            ulonglong2 w2 = *reinterpret_cast<const ulonglong2*>(wrow + (4 * f4 + 2) * 64);
            ulonglong2 w3 = *reinterpret_cast<const ulonglong2*>(wrow + (4 * f4 + 3) * 64);
            #pragma unroll
            for (int a = 0; a < CHUNK; a++) {
                const float* swa = sw + a * SS_PER_ATOM + 4 * f4;
                float4 vx = *reinterpret_cast<const float4*>(swa);
                float4 vy = *reinterpret_cast<const float4*>(swa + FDIM);
                float4 vz = *reinterpret_cast<const float4*>(swa + 2 * FDIM);
                ull d;
                d = dup2(vx.x); FMA2(acc[a*6+0], d, w0.x); FMA2(acc[a*6+1], d, w0.y);
                d = dup2(vy.x); FMA2(acc[a*6+2], d, w0.x); FMA2(acc[a*6+3], d, w0.y);
                d = dup2(vz.x); FMA2(acc[a*6+4], d, w0.x); FMA2(acc[a*6+5], d, w0.y);
                d = dup2(vx.y); FMA2(acc[a*6+0], d, w1.x); FMA2(acc[a*6+1], d, w1.y);
                d = dup2(vy.y); FMA2(acc[a*6+2], d, w1.x); FMA2(acc[a*6+3], d, w1.y);
                d = dup2(vz.y); FMA2(acc[a*6+4], d, w1.x); FMA2(acc[a*6+5], d, w1.y);
                d = dup2(vx.z); FMA2(acc[a*6+0], d, w2.x); FMA2(acc[a*6+1], d, w2.y);
                d = dup2(vy.z); FMA2(acc[a*6+2], d, w2.x); FMA2(acc[a*6+3], d, w2.y);
                d = dup2(vz.z); FMA2(acc[a*6+4], d, w2.x); FMA2(acc[a*6+5], d, w2.y);
                d = dup2(vx.w); FMA2(acc[a*6+0], d, w3.x); FMA2(acc[a*6+1], d, w3.y);
                d = dup2(vy.w); FMA2(acc[a*6+2], d, w3.x); FMA2(acc[a*6+3], d, w3.y);
                d = dup2(vz.w); FMA2(acc[a*6+4], d, w3.x); FMA2(acc[a*6+5], d, w3.y);
            }
        }

        // ================= epilogue: bias + norm + store ===================
        float4 bb = __ldg(reinterpret_cast<const float4*>(bvec + fbase));
        #pragma unroll
        for (int a = 0; a < CHUNK; a++) {
            const int atom = abase + a;
            if (atom >= n_atoms) break;
            float tx[4], ty[4], tz[4];
            unpack2(acc[a*6+0], tx[0], tx[1]); unpack2(acc[a*6+1], tx[2], tx[3]);
            unpack2(acc[a*6+2], ty[0], ty[1]); unpack2(acc[a*6+3], ty[2], ty[3]);
            unpack2(acc[a*6+4], tz[0], tz[1]); unpack2(acc[a*6+5], tz[2], tz[3]);
            float bbv[4] = {bb.x, bb.y, bb.z, bb.w};
            float4 nrm;
            float* nv = &nrm.x;
            #pragma unroll
            for (int k = 0; k < 4; k++) {
                float db = degs[a] * bbv[k];
                float x = tx[k] + db;
                float y = ty[k] + db;
                float z = tz[k] + db;
                nv[k] = sqrtf(x * x + y * y + z * z + 1e-12f);
            }
            *reinterpret_cast<float4*>(out + (size_t)atom * (2 * FDIM) + fbase) = nrm;
        }
    }
}

// ---------------------------------------------------------------------------
extern "C" void kernel_launch(void* const* d_in, const int* in_sizes, int n_in,
                              void* d_out, int out_size) {
    const float* A   = (const float*)d_in[0];
    const int*   pl  = (const int*)d_in[1];
    const float* fc  = (const float*)d_in[2];
    const float* rij = (const float*)d_in[3];
    const float* W   = (const float*)d_in[4];
    const float* b   = (const float*)d_in[5];
    float* out = (float*)d_out;

    int n_atoms = in_sizes[0] / FDIM;
    int n_pairs = in_sizes[2];

    static int smem_set = 0;
    if (!smem_set) {
        cudaFuncSetAttribute(main_kernel,
                             cudaFuncAttributeMaxDynamicSharedMemorySize, SMEM_MAIN);
        smem_set = 1;
    }

    int pb = (n_pairs + 255) / 256;
    zero_counts_kernel<<<(n_atoms + 256) / 256, 256>>>(n_atoms);
    hist_kernel<<<pb, 256>>>(pl, n_pairs);
    scan_kernel<<<1, 1024>>>(n_atoms);
    scatter_kernel<<<pb, 256>>>(pl, n_pairs);
    main_kernel<<<MAIN_BLOCKS, MAIN_THREADS, SMEM_MAIN>>>(
        A, pl, fc, rij, W, b, out, n_pairs, n_atoms);
}